// round 8
// baseline (speedup 1.0000x reference)
#include <cuda_runtime.h>

// Trilinear resize [4,128,128,128,2] -> [4,192,192,192,2], zoom 1.5/axis.
// 3x3x3 output tile per thread (9 LDG.128 -> 27 float2 outputs).
// w=64 boundary values published by the paired half-1 warp's lane 0 via smem;
// synchronization is a NAMED barrier over just the 64-thread warp pair
// (block-wide __syncthreads in R7 serialized all 8 warps and cost 2.3us).
// Stores staged per-warp in smem -> coalesced STG.128 (full 32B sectors).

#define IN_S   128
#define OUT_S  192

static constexpr float INV15 = 1.0f / 1.5f;

__device__ __forceinline__ float2 lerp2(float w0, float2 a, float w1, float2 b) {
    return make_float2(w0 * a.x + w1 * b.x, w0 * a.y + w1 * b.y);
}

__device__ __forceinline__ void pair_barrier(int id) {
    asm volatile("bar.sync %0, 64;" :: "r"(id) : "memory");
}

__global__ void __launch_bounds__(256, 4)
resize_tile333_nb_kernel(const float4* __restrict__ in4,
                         float4* __restrict__ out4) {
    __shared__ float  sbuf[8][3][192];       // 8 warps x 3 j-rows x 768B = 18KB
    __shared__ float2 bshare[4][9];          // per warp-pair: w=64 values, 9 rows

    const int lane = threadIdx.x;            // 0..31
    const int ty   = threadIdx.y;            // 0..7 (warp id)
    const int half = ty & 1;                 // k half
    const int nsub = ty >> 1;                // j-period sub-index 0..3
    const int m    = half * 32 + lane;       // k-period 0..63
    const int n    = blockIdx.x * 4 + nsub;  // j-period 0..63
    const int q    = blockIdx.y;             // i-period 0..63
    const int b    = blockIdx.z;

    // ---- i weights (warp-uniform)
    const int p2c = min(2 * q + 2, 127);
    float li1 = (float)(3 * q + 1) * INV15;
    float wi1_0 = (float)(2 * q + 1) - li1;
    float wi1_1 = 1.0f - wi1_0;
    float li2 = fminf((float)(3 * q + 2) * INV15, 127.0f);
    float wi2_0 = (float)p2c - li2;
    float wi2_1 = 1.0f - wi2_0;

    // ---- j weights (warp-uniform)
    const int h2c = min(2 * n + 2, 127);
    float lj1 = (float)(3 * n + 1) * INV15;
    float wj1_0 = (float)(2 * n + 1) - lj1;
    float wj1_1 = 1.0f - wj1_0;
    float lj2 = fminf((float)(3 * n + 2) * INV15, 127.0f);
    float wj2_0 = (float)h2c - lj2;
    float wj2_1 = 1.0f - wj2_0;

    // ---- k weights (per lane)
    float lka = (float)(3 * m + 1) * INV15;
    float wk1_0 = (float)(2 * m + 1) - lka;
    float wk1_1 = 1.0f - wk1_0;
    int   w2c  = min(2 * m + 2, 127);
    float lkb = fminf((float)(3 * m + 2) * INV15, 127.0f);
    float wk2_0 = (float)w2c - lkb;
    float wk2_1 = 1.0f - wk2_0;

    // ---- gather: 9 x LDG.128 (3 planes x 3 h-rows), w = 2m & 2m+1
    const float4* p4 = in4 + (size_t)b * (IN_S * IN_S * (IN_S / 2));
    const int pl0 = 2 * q, pl1 = 2 * q + 1;
    const int hr0 = 2 * n, hr1 = 2 * n + 1;

    int r00 = (pl0 * IN_S + hr0) * (IN_S / 2);
    int r01 = (pl0 * IN_S + hr1) * (IN_S / 2);
    int r02 = (pl0 * IN_S + h2c) * (IN_S / 2);
    int r10 = (pl1 * IN_S + hr0) * (IN_S / 2);
    int r11 = (pl1 * IN_S + hr1) * (IN_S / 2);
    int r12 = (pl1 * IN_S + h2c) * (IN_S / 2);
    int r20 = (p2c * IN_S + hr0) * (IN_S / 2);
    int r21 = (p2c * IN_S + hr1) * (IN_S / 2);
    int r22 = (p2c * IN_S + h2c) * (IN_S / 2);

    float4 P00 = __ldg(p4 + r00 + m);
    float4 P01 = __ldg(p4 + r01 + m);
    float4 P02 = __ldg(p4 + r02 + m);
    float4 P10 = __ldg(p4 + r10 + m);
    float4 P11 = __ldg(p4 + r11 + m);
    float4 P12 = __ldg(p4 + r12 + m);
    float4 P20 = __ldg(p4 + r20 + m);
    float4 P21 = __ldg(p4 + r21 + m);
    float4 P22 = __ldg(p4 + r22 + m);

    // ---- half-1 lane-0 (m=32: w=64,65) publishes w=64 values for the
    //      boundary lane (lane31/half0, m=31 needs w=64). Bit-exact.
    if (half == 1 && lane == 0) {
        bshare[nsub][0] = make_float2(P00.x, P00.y);
        bshare[nsub][1] = make_float2(P01.x, P01.y);
        bshare[nsub][2] = make_float2(P02.x, P02.y);
        bshare[nsub][3] = make_float2(P10.x, P10.y);
        bshare[nsub][4] = make_float2(P11.x, P11.y);
        bshare[nsub][5] = make_float2(P12.x, P12.y);
        bshare[nsub][6] = make_float2(P20.x, P20.y);
        bshare[nsub][7] = make_float2(P21.x, P21.y);
        bshare[nsub][8] = make_float2(P22.x, P22.y);
    }
    pair_barrier(nsub + 1);                  // sync only the 2-warp pair

    const bool bnd = (lane == 31) && (half == 0);
    const int obase = (b * OUT_S + 3 * q) * OUT_S + 3 * n;   // (i,j) row origin

    #pragma unroll
    for (int ir = 0; ir < 3; ir++) {
        // ---- d-interp: t[h-row][wpos0/1] + boundary tb[h-row] (bnd lane only)
        float2 t00_, t01_, t10_, t11_, t20_, t21_;
        float2 tb0, tb1, tb2;
        if (ir == 0) {
            t00_ = make_float2(P00.x, P00.y); t01_ = make_float2(P00.z, P00.w);
            t10_ = make_float2(P01.x, P01.y); t11_ = make_float2(P01.z, P01.w);
            t20_ = make_float2(P02.x, P02.y); t21_ = make_float2(P02.z, P02.w);
            if (bnd) {
                tb0 = bshare[nsub][0]; tb1 = bshare[nsub][1]; tb2 = bshare[nsub][2];
            }
        } else if (ir == 1) {
            t00_ = lerp2(wi1_0, make_float2(P00.x,P00.y), wi1_1, make_float2(P10.x,P10.y));
            t01_ = lerp2(wi1_0, make_float2(P00.z,P00.w), wi1_1, make_float2(P10.z,P10.w));
            t10_ = lerp2(wi1_0, make_float2(P01.x,P01.y), wi1_1, make_float2(P11.x,P11.y));
            t11_ = lerp2(wi1_0, make_float2(P01.z,P01.w), wi1_1, make_float2(P11.z,P11.w));
            t20_ = lerp2(wi1_0, make_float2(P02.x,P02.y), wi1_1, make_float2(P12.x,P12.y));
            t21_ = lerp2(wi1_0, make_float2(P02.z,P02.w), wi1_1, make_float2(P12.z,P12.w));
            if (bnd) {
                tb0 = lerp2(wi1_0, bshare[nsub][0], wi1_1, bshare[nsub][3]);
                tb1 = lerp2(wi1_0, bshare[nsub][1], wi1_1, bshare[nsub][4]);
                tb2 = lerp2(wi1_0, bshare[nsub][2], wi1_1, bshare[nsub][5]);
            }
        } else {
            t00_ = lerp2(wi2_0, make_float2(P10.x,P10.y), wi2_1, make_float2(P20.x,P20.y));
            t01_ = lerp2(wi2_0, make_float2(P10.z,P10.w), wi2_1, make_float2(P20.z,P20.w));
            t10_ = lerp2(wi2_0, make_float2(P11.x,P11.y), wi2_1, make_float2(P21.x,P21.y));
            t11_ = lerp2(wi2_0, make_float2(P11.z,P11.w), wi2_1, make_float2(P21.z,P21.w));
            t20_ = lerp2(wi2_0, make_float2(P12.x,P12.y), wi2_1, make_float2(P22.x,P22.y));
            t21_ = lerp2(wi2_0, make_float2(P12.z,P12.w), wi2_1, make_float2(P22.z,P22.w));
            if (bnd) {
                tb0 = lerp2(wi2_0, bshare[nsub][3], wi2_1, bshare[nsub][6]);
                tb1 = lerp2(wi2_0, bshare[nsub][4], wi2_1, bshare[nsub][7]);
                tb2 = lerp2(wi2_0, bshare[nsub][5], wi2_1, bshare[nsub][8]);
            }
        }

        // ---- h-interp per j-row, then k-interp; stage to smem
        #pragma unroll
        for (int jr = 0; jr < 3; jr++) {
            float2 u0, u1, ub;
            if (jr == 0)      { u0 = t00_; u1 = t01_; ub = tb0; }
            else if (jr == 1) {
                u0 = lerp2(wj1_0, t00_, wj1_1, t10_);
                u1 = lerp2(wj1_0, t01_, wj1_1, t11_);
                ub = lerp2(wj1_0, tb0,  wj1_1, tb1);
            } else {
                u0 = lerp2(wj2_0, t10_, wj2_1, t20_);
                u1 = lerp2(wj2_0, t11_, wj2_1, t21_);
                ub = lerp2(wj2_0, tb1,  wj2_1, tb2);
            }
            float2 u2;
            u2.x = __shfl_down_sync(0xffffffffu, u0.x, 1);
            u2.y = __shfl_down_sync(0xffffffffu, u0.y, 1);
            if (lane == 31) u2 = (half == 1) ? u1 : ub;

            float2* s = (float2*)sbuf[ty][jr];
            s[lane * 3 + 0] = u0;
            s[lane * 3 + 1] = lerp2(wk1_0, u0, wk1_1, u1);
            s[lane * 3 + 2] = lerp2(wk2_0, u1, wk2_1, u2);
        }
        __syncwarp();

        // ---- coalesced STG.128: 3 j-rows x 48 float4 per warp
        #pragma unroll
        for (int jr = 0; jr < 3; jr++) {
            const float4* s4 = (const float4*)sbuf[ty][jr];
            int base4 = (obase + ir * OUT_S + jr) * (OUT_S / 2) + half * 48;
            out4[base4 + lane] = s4[lane];
            if (lane < 16) out4[base4 + 32 + lane] = s4[32 + lane];
        }
        __syncwarp();
    }
}

extern "C" void kernel_launch(void* const* d_in, const int* in_sizes, int n_in,
                              void* d_out, int out_size) {
    const float4* in4 = (const float4*)d_in[0];
    float4*       out = (float4*)d_out;
    dim3 block(32, 8);                   // 256 threads
    dim3 grid(OUT_S / 12, OUT_S / 3, 4); // (16, 64, 4) = 4096 blocks
    resize_tile333_nb_kernel<<<grid, block>>>(in4, out);
}